// round 5
// baseline (speedup 1.0000x reference)
#include <cuda_runtime.h>

#define NODES 100000
#define NEDGES 3200000
#define DD 20

// ---------------- static device scratch (no allocations allowed) ----------------
__device__ int   d_cnt[2 * NODES];        // [0:N) icnt, [N:2N) ocnt  (one memset)
__device__ int   d_rowptr[NODES + 1];
__device__ int   d_cursor[NODES];
__device__ int   d_col[NEDGES];
__device__ float d_din[NODES];
__device__ float d_dout[NODES];
__device__ float d_g0[NODES];
__device__ float d_gA[NODES * DD];
__device__ float d_gB[NODES * DD];

// ---------------- graph build ----------------
__global__ void k_hist(const int* __restrict__ src, const int* __restrict__ dst) {
    int e = blockIdx.x * blockDim.x + threadIdx.x;
    if (e < NEDGES) {
        atomicAdd(&d_cnt[NODES + src[e]], 1);   // out-degree
        atomicAdd(&d_cnt[dst[e]], 1);           // in-degree
    }
}

// exclusive scan of icnt -> rowptr, fused with per-node init (cursor/din/dout/g0)
__global__ void k_scan_init(const float* __restrict__ feat) {
    __shared__ int part[1024];
    const int CH = (NODES + 1023) / 1024;  // 98
    int tid = threadIdx.x;
    int s0 = tid * CH;
    int s1 = s0 + CH; if (s1 > NODES) s1 = NODES; if (s0 > NODES) s0 = NODES;
    int sum = 0;
    for (int i = s0; i < s1; i++) sum += d_cnt[i];
    part[tid] = sum;
    __syncthreads();
    for (int off = 1; off < 1024; off <<= 1) {
        int v = (tid >= off) ? part[tid - off] : 0;
        __syncthreads();
        part[tid] += v;
        __syncthreads();
    }
    int run = (tid > 0) ? part[tid - 1] : 0;
    for (int i = s0; i < s1; i++) {
        int ic = d_cnt[i];
        d_rowptr[i] = run;
        d_cursor[i] = run;
        float di = rsqrtf((float)(ic + 1));                 // +1 self-loop
        float dq = rsqrtf((float)(d_cnt[NODES + i] + 1));
        d_din[i]  = di;
        d_dout[i] = dq;
        d_g0[i]   = feat[i] * dq;                           // layer-0 source values
        run += ic;
    }
    if (tid == 1023) d_rowptr[NODES] = part[1023];
}

__global__ void k_scatter(const int* __restrict__ src, const int* __restrict__ dst) {
    int e = blockIdx.x * blockDim.x + threadIdx.x;
    if (e < NEDGES) {
        int p = atomicAdd(&d_cursor[dst[e]], 1);
        d_col[p] = src[e];
    }
}

// ---------------- layer 0 : scalar aggregation, D_in = 1 ----------------
__global__ void __launch_bounds__(256)
k_layer0(const float* __restrict__ W, const float* __restrict__ b) {
    const unsigned FULL = 0xffffffffu;
    int lane = threadIdx.x & 31;
    int w    = (blockIdx.x * blockDim.x + threadIdx.x) >> 5;
    int nw   = (gridDim.x * blockDim.x) >> 5;
    int tt   = lane < DD ? lane : 0;
    float wt = W[tt];
    float bt = b[tt];
    for (int n = w; n < NODES; n += nw) {
        int beg = d_rowptr[n], end = d_rowptr[n + 1];
        float acc = (lane == 0) ? d_g0[n] : 0.f;     // self-loop
        for (int j = beg + lane; j < end; j += 32)
            acc += __ldg(&d_g0[__ldg(&d_col[j])]);
        #pragma unroll
        for (int off = 16; off; off >>= 1)
            acc += __shfl_xor_sync(FULL, acc, off);
        if (lane < DD) {
            float r = fmaf(d_din[n] * acc, wt, bt);
            r = fmaxf(r, 0.f);
            d_gA[n * DD + lane] = r * d_dout[n];     // store g = h * dout
        }
    }
}

// ---------------- fused layer: aggregate(g) -> @W -> *din +b -> (relu) -> (*dout) ----
// W lives in SHARED memory (frees ~20 regs -> 8 blocks/SM residency).
template <int RELU, int SCALE>
__device__ __forceinline__ void layer_body(const float* __restrict__ gin,
                                           float* __restrict__ gout,
                                           const float* __restrict__ W,
                                           const float* __restrict__ b) {
    const unsigned FULL = 0xffffffffu;
    __shared__ float Wsm[DD * DD];
    for (int i = threadIdx.x; i < DD * DD; i += blockDim.x) Wsm[i] = W[i];
    __syncthreads();

    int lane = threadIdx.x & 31;
    int w    = (blockIdx.x * blockDim.x + threadIdx.x) >> 5;
    int nw   = (gridDim.x * blockDim.x) >> 5;
    // lane layout for aggregation: 6 edges x 5 float4 chunks (lanes 30,31 idle)
    int c    = lane % 5;
    int esub = lane / 5;
    bool lok = lane < 30;
    int tt = lane < DD ? lane : 0;
    float bt = b[tt];
    const float4* gin4 = (const float4*)gin;   // packed rows: 5 float4 / node

    for (int n = w; n < NODES; n += nw) {
        int beg = d_rowptr[n], end = d_rowptr[n + 1];
        float4 acc = make_float4(0.f, 0.f, 0.f, 0.f);
        if (lok && esub == 0) acc = __ldg(&gin4[n * 5 + c]);   // self-loop

        // ---- main loop: 12 edges / body, 2 rows in flight per lane ----
        int j0 = beg;
        if (lok) {
            for (; j0 + 12 <= end; j0 += 12) {
                int jj = j0 + esub;
                int s0 = __ldg(&d_col[jj]);
                int s1 = __ldg(&d_col[jj + 6]);
                float4 x0 = __ldg(&gin4[s0 * 5 + c]);
                float4 x1 = __ldg(&gin4[s1 * 5 + c]);
                acc.x += x0.x; acc.y += x0.y; acc.z += x0.z; acc.w += x0.w;
                acc.x += x1.x; acc.y += x1.y; acc.z += x1.z; acc.w += x1.w;
            }
        } else {
            j0 = end - ((end - beg) % 12);           // loop-exit-consistent for lanes 30,31
            if (j0 < beg) j0 = beg;
        }

        // ---- remainder: up to 11 edges, predicated ----
        #pragma unroll 2
        for (; j0 < end; j0 += 6) {
            int j = j0 + esub;
            if (lok && j < end) {
                int s = __ldg(&d_col[j]);
                float4 x = __ldg(&gin4[s * 5 + c]);
                acc.x += x.x; acc.y += x.y; acc.z += x.z; acc.w += x.w;
            }
        }

        // Reduce the 6 edge groups (stride 5), predicated folds (no double count):
        //   step1: lanes 0..14 += lanes 15..29 ; step2: lanes 0..4 += lanes 10..14 ;
        //   step3: lanes 0..4 += lanes 5..9
        float4 t;
        t.x = __shfl_down_sync(FULL, acc.x, 15);
        t.y = __shfl_down_sync(FULL, acc.y, 15);
        t.z = __shfl_down_sync(FULL, acc.z, 15);
        t.w = __shfl_down_sync(FULL, acc.w, 15);
        if (lane < 15) { acc.x += t.x; acc.y += t.y; acc.z += t.z; acc.w += t.w; }
        t.x = __shfl_down_sync(FULL, acc.x, 10);
        t.y = __shfl_down_sync(FULL, acc.y, 10);
        t.z = __shfl_down_sync(FULL, acc.z, 10);
        t.w = __shfl_down_sync(FULL, acc.w, 10);
        if (lane < 5) { acc.x += t.x; acc.y += t.y; acc.z += t.z; acc.w += t.w; }
        t.x = __shfl_down_sync(FULL, acc.x, 5);
        t.y = __shfl_down_sync(FULL, acc.y, 5);
        t.z = __shfl_down_sync(FULL, acc.z, 5);
        t.w = __shfl_down_sync(FULL, acc.w, 5);
        if (lane < 5) { acc.x += t.x; acc.y += t.y; acc.z += t.z; acc.w += t.w; }

        // lane c holds s[4c..4c+3]; broadcast + matvec out[tt] = sum_k s[k]*W[k][tt]
        float m = 0.f;
        #pragma unroll
        for (int k = 0; k < DD; k++) {
            float comp = ((k & 3) == 0) ? acc.x :
                         ((k & 3) == 1) ? acc.y :
                         ((k & 3) == 2) ? acc.z : acc.w;
            float sk = __shfl_sync(FULL, comp, k >> 2);
            m = fmaf(sk, Wsm[k * DD + tt], m);
        }
        if (lane < DD) {
            float r = fmaf(d_din[n], m, bt);
            if (RELU)  r = fmaxf(r, 0.f);
            if (SCALE) r *= d_dout[n];
            gout[n * DD + lane] = r;
        }
    }
}

__global__ void __launch_bounds__(256)
k_layer_mid(const float* __restrict__ W, const float* __restrict__ b, int cur) {
    const float* gin = cur ? d_gB : d_gA;
    float* gout      = cur ? d_gA : d_gB;
    layer_body<1, 1>(gin, gout, W, b);
}

__global__ void __launch_bounds__(256)
k_layer_final(const float* __restrict__ W, const float* __restrict__ b,
              int cur, float* __restrict__ out) {
    const float* gin = cur ? d_gB : d_gA;
    layer_body<0, 0>(gin, out, W, b);
}

// ---------------- launch ----------------
#define LGRID 1184   // 8 blocks/SM x 148 SMs -> 64 warps/SM when regs permit

extern "C" void kernel_launch(void* const* d_in, const int* in_sizes, int n_in,
                              void* d_out, int out_size) {
    const float* feat = (const float*)d_in[0];
    const float* Ws   = (const float*)d_in[1];
    const float* bs   = (const float*)d_in[2];
    const float* Wm   = (const float*)d_in[3];
    const float* bm   = (const float*)d_in[4];
    const float* Wf   = (const float*)d_in[5];
    const float* bf   = (const float*)d_in[6];
    const int*   src  = (const int*)d_in[7];
    const int*   dst  = (const int*)d_in[8];
    float* out = (float*)d_out;

    // zero both degree counters with one async memset (graph-capturable)
    void* p_cnt = nullptr;
    cudaGetSymbolAddress(&p_cnt, d_cnt);
    cudaMemsetAsync(p_cnt, 0, 2 * NODES * sizeof(int));

    // graph build (CSR grouped by dst, self-loops implicit)
    k_hist     <<<(NEDGES + 255) / 256, 256>>>(src, dst);
    k_scan_init<<<1, 1024>>>(feat);
    k_scatter  <<<(NEDGES + 255) / 256, 256>>>(src, dst);

    // 20 conv layers, one fused kernel each
    k_layer0<<<LGRID, 256>>>(Ws, bs);                // writes d_gA
    int cur = 0;                                      // 0: current in gA
    for (int k = 0; k < 18; k++) {
        k_layer_mid<<<LGRID, 256>>>(Wm + k * DD * DD, bm + k * DD, cur);
        cur ^= 1;
    }
    k_layer_final<<<LGRID, 256>>>(Wf, bf, cur, out);
}

// round 6
// speedup vs baseline: 1.0205x; 1.0205x over previous
#include <cuda_runtime.h>

#define NODES 100000
#define NEDGES 3200000
#define DD 20
#define GSTR 32   // padded row stride (floats): 128B rows, each gather = 1 L1 line

// ---------------- static device scratch (no allocations allowed) ----------------
__device__ int   d_cnt[2 * NODES];        // [0:N) icnt, [N:2N) ocnt  (one memset)
__device__ int   d_rowptr[NODES + 1];
__device__ int   d_cursor[NODES];
__device__ int   d_col[NEDGES];
__device__ float d_din[NODES];
__device__ float d_dout[NODES];
__device__ float d_g0[NODES];
__device__ float d_gA[NODES * GSTR];
__device__ float d_gB[NODES * GSTR];

// ---------------- graph build ----------------
__global__ void k_hist(const int* __restrict__ src, const int* __restrict__ dst) {
    int e = blockIdx.x * blockDim.x + threadIdx.x;
    if (e < NEDGES) {
        atomicAdd(&d_cnt[NODES + src[e]], 1);   // out-degree
        atomicAdd(&d_cnt[dst[e]], 1);           // in-degree
    }
}

// exclusive scan of icnt -> rowptr, fused with per-node init (cursor/din/dout/g0)
__global__ void k_scan_init(const float* __restrict__ feat) {
    __shared__ int part[1024];
    const int CH = (NODES + 1023) / 1024;  // 98
    int tid = threadIdx.x;
    int s0 = tid * CH;
    int s1 = s0 + CH; if (s1 > NODES) s1 = NODES; if (s0 > NODES) s0 = NODES;
    int sum = 0;
    for (int i = s0; i < s1; i++) sum += d_cnt[i];
    part[tid] = sum;
    __syncthreads();
    for (int off = 1; off < 1024; off <<= 1) {
        int v = (tid >= off) ? part[tid - off] : 0;
        __syncthreads();
        part[tid] += v;
        __syncthreads();
    }
    int run = (tid > 0) ? part[tid - 1] : 0;
    for (int i = s0; i < s1; i++) {
        int ic = d_cnt[i];
        d_rowptr[i] = run;
        d_cursor[i] = run;
        float di = rsqrtf((float)(ic + 1));                 // +1 self-loop
        float dq = rsqrtf((float)(d_cnt[NODES + i] + 1));
        d_din[i]  = di;
        d_dout[i] = dq;
        d_g0[i]   = feat[i] * dq;                           // layer-0 source values
        run += ic;
    }
    if (tid == 1023) d_rowptr[NODES] = part[1023];
}

__global__ void k_scatter(const int* __restrict__ src, const int* __restrict__ dst) {
    int e = blockIdx.x * blockDim.x + threadIdx.x;
    if (e < NEDGES) {
        int p = atomicAdd(&d_cursor[dst[e]], 1);
        d_col[p] = src[e];
    }
}

// ---------------- layer 0 : scalar aggregation, D_in = 1 ----------------
__global__ void __launch_bounds__(256)
k_layer0(const float* __restrict__ W, const float* __restrict__ b) {
    const unsigned FULL = 0xffffffffu;
    int lane = threadIdx.x & 31;
    int w    = (blockIdx.x * blockDim.x + threadIdx.x) >> 5;
    int nw   = (gridDim.x * blockDim.x) >> 5;
    int tt   = lane < DD ? lane : 0;
    float wt = W[tt];
    float bt = b[tt];
    for (int n = w; n < NODES; n += nw) {
        int beg = d_rowptr[n], end = d_rowptr[n + 1];
        float acc = (lane == 0) ? d_g0[n] : 0.f;     // self-loop
        for (int j = beg + lane; j < end; j += 32)
            acc += __ldg(&d_g0[__ldg(&d_col[j])]);
        #pragma unroll
        for (int off = 16; off; off >>= 1)
            acc += __shfl_xor_sync(FULL, acc, off);
        if (lane < DD) {
            float r = fmaf(d_din[n] * acc, wt, bt);
            r = fmaxf(r, 0.f);
            d_gA[n * GSTR + lane] = r * d_dout[n];   // store g = h*dout (padded row)
        }
    }
}

// ---------------- fused layer: aggregate(g) -> @W -> *din +b -> (relu) -> (*dout) ----
// gin rows GSTR-padded (1 L1 line per gather). W column in registers.
// Broadcast of the reduced s-vector goes through per-warp smem (1 STS + 5 LDS.128
// broadcasts instead of 20 shfls) to cut MIO pressure.
template <int RELU, int SCALE, int OSTR>
__device__ __forceinline__ void layer_body(const float* __restrict__ gin,
                                           float* __restrict__ gout,
                                           const float* __restrict__ W,
                                           const float* __restrict__ b) {
    const unsigned FULL = 0xffffffffu;
    __shared__ __align__(16) float ssm[8][DD];      // per-warp staging (8 warps/block)

    int lane = threadIdx.x & 31;
    int wid  = threadIdx.x >> 5;
    int w    = (blockIdx.x * blockDim.x + threadIdx.x) >> 5;
    int nw   = (gridDim.x * blockDim.x) >> 5;
    // lane layout for aggregation: 6 edges x 5 float4 chunks (lanes 30,31 idle)
    int c    = lane % 5;
    int esub = lane / 5;
    bool lok = lane < 30;
    int tt = lane < DD ? lane : 0;
    float wcol[DD];
    #pragma unroll
    for (int k = 0; k < DD; k++) wcol[k] = W[k * DD + tt];
    float bt = b[tt];
    const float4* gin4 = (const float4*)gin;        // 8 float4 per padded row
    float4* swarp = (float4*)ssm[wid];

    for (int n = w; n < NODES; n += nw) {
        int beg = d_rowptr[n], end = d_rowptr[n + 1];
        float4 acc = make_float4(0.f, 0.f, 0.f, 0.f);
        if (lok && esub == 0) acc = __ldg(&gin4[(n << 3) + c]);   // self-loop

        // ---- main loop: 12 edges / body, 2 rows in flight per lane ----
        int j0 = beg;
        if (lok) {
            for (; j0 + 12 <= end; j0 += 12) {
                int jj = j0 + esub;
                int s0 = __ldg(&d_col[jj]);
                int s1 = __ldg(&d_col[jj + 6]);
                float4 x0 = __ldg(&gin4[(s0 << 3) + c]);
                float4 x1 = __ldg(&gin4[(s1 << 3) + c]);
                acc.x += x0.x; acc.y += x0.y; acc.z += x0.z; acc.w += x0.w;
                acc.x += x1.x; acc.y += x1.y; acc.z += x1.z; acc.w += x1.w;
            }
        } else {
            j0 = end - ((end - beg) % 12);           // loop-exit-consistent for lanes 30,31
            if (j0 < beg) j0 = beg;
        }

        // ---- remainder: up to 11 edges, predicated ----
        #pragma unroll 2
        for (; j0 < end; j0 += 6) {
            int j = j0 + esub;
            if (lok && j < end) {
                int s = __ldg(&d_col[j]);
                float4 x = __ldg(&gin4[(s << 3) + c]);
                acc.x += x.x; acc.y += x.y; acc.z += x.z; acc.w += x.w;
            }
        }

        // Reduce the 6 edge groups (stride 5), predicated folds (no double count):
        float4 t;
        t.x = __shfl_down_sync(FULL, acc.x, 15);
        t.y = __shfl_down_sync(FULL, acc.y, 15);
        t.z = __shfl_down_sync(FULL, acc.z, 15);
        t.w = __shfl_down_sync(FULL, acc.w, 15);
        if (lane < 15) { acc.x += t.x; acc.y += t.y; acc.z += t.z; acc.w += t.w; }
        t.x = __shfl_down_sync(FULL, acc.x, 10);
        t.y = __shfl_down_sync(FULL, acc.y, 10);
        t.z = __shfl_down_sync(FULL, acc.z, 10);
        t.w = __shfl_down_sync(FULL, acc.w, 10);
        if (lane < 5) { acc.x += t.x; acc.y += t.y; acc.z += t.z; acc.w += t.w; }
        t.x = __shfl_down_sync(FULL, acc.x, 5);
        t.y = __shfl_down_sync(FULL, acc.y, 5);
        t.z = __shfl_down_sync(FULL, acc.z, 5);
        t.w = __shfl_down_sync(FULL, acc.w, 5);
        if (lane < 5) { acc.x += t.x; acc.y += t.y; acc.z += t.z; acc.w += t.w; }

        // Broadcast s via per-warp smem: lanes 0-4 STS.128, then LDS.128 broadcasts.
        if (lane < 5) swarp[lane] = acc;
        __syncwarp(FULL);
        float m = 0.f;
        #pragma unroll
        for (int c2 = 0; c2 < 5; c2++) {
            float4 sv = swarp[c2];                   // same address all lanes: broadcast
            m = fmaf(sv.x, wcol[4 * c2 + 0], m);
            m = fmaf(sv.y, wcol[4 * c2 + 1], m);
            m = fmaf(sv.z, wcol[4 * c2 + 2], m);
            m = fmaf(sv.w, wcol[4 * c2 + 3], m);
        }
        __syncwarp(FULL);                            // protect staging from next node's STS
        if (lane < DD) {
            float r = fmaf(d_din[n], m, bt);
            if (RELU)  r = fmaxf(r, 0.f);
            if (SCALE) r *= d_dout[n];
            gout[n * OSTR + lane] = r;
        }
    }
}

__global__ void __launch_bounds__(256, 5)
k_layer_mid(const float* __restrict__ W, const float* __restrict__ b, int cur) {
    const float* gin = cur ? d_gB : d_gA;
    float* gout      = cur ? d_gA : d_gB;
    layer_body<1, 1, GSTR>(gin, gout, W, b);
}

__global__ void __launch_bounds__(256, 5)
k_layer_final(const float* __restrict__ W, const float* __restrict__ b,
              int cur, float* __restrict__ out) {
    const float* gin = cur ? d_gB : d_gA;
    layer_body<0, 0, DD>(gin, out, W, b);
}

// ---------------- launch ----------------
#define LGRID 1184

extern "C" void kernel_launch(void* const* d_in, const int* in_sizes, int n_in,
                              void* d_out, int out_size) {
    const float* feat = (const float*)d_in[0];
    const float* Ws   = (const float*)d_in[1];
    const float* bs   = (const float*)d_in[2];
    const float* Wm   = (const float*)d_in[3];
    const float* bm   = (const float*)d_in[4];
    const float* Wf   = (const float*)d_in[5];
    const float* bf   = (const float*)d_in[6];
    const int*   src  = (const int*)d_in[7];
    const int*   dst  = (const int*)d_in[8];
    float* out = (float*)d_out;

    // zero both degree counters with one async memset (graph-capturable)
    void* p_cnt = nullptr;
    cudaGetSymbolAddress(&p_cnt, d_cnt);
    cudaMemsetAsync(p_cnt, 0, 2 * NODES * sizeof(int));

    // graph build (CSR grouped by dst, self-loops implicit)
    k_hist     <<<(NEDGES + 255) / 256, 256>>>(src, dst);
    k_scan_init<<<1, 1024>>>(feat);
    k_scatter  <<<(NEDGES + 255) / 256, 256>>>(src, dst);

    // 20 conv layers, one fused kernel each
    k_layer0<<<LGRID, 256>>>(Ws, bs);                // writes d_gA (padded)
    int cur = 0;                                      // 0: current in gA
    for (int k = 0; k < 18; k++) {
        k_layer_mid<<<LGRID, 256>>>(Wm + k * DD * DD, bm + k * DD, cur);
        cur ^= 1;
    }
    k_layer_final<<<LGRID, 256>>>(Wf, bf, cur, out);
}

// round 7
// speedup vs baseline: 1.1175x; 1.0950x over previous
#include <cuda_runtime.h>

#define NODES 100000
#define NEDGES 3200000
#define DD 20
#define GSTR 32   // padded row stride (floats): 128B rows, each gather = 1 L1 line

// ---------------- static device scratch (no allocations allowed) ----------------
__device__ int   d_cnt[2 * NODES];        // [0:N) icnt, [N:2N) ocnt  (one memset)
__device__ int   d_rowptr[NODES + 1];
__device__ int   d_cursor[NODES];
__device__ int   d_col[NEDGES];
__device__ float d_din[NODES];
__device__ float d_dout[NODES];
__device__ float d_g0[NODES];
__device__ float d_gA[NODES * GSTR];
__device__ float d_gB[NODES * GSTR];

// ---------------- graph build ----------------
__global__ void k_hist(const int* __restrict__ src, const int* __restrict__ dst) {
    int e = blockIdx.x * blockDim.x + threadIdx.x;
    if (e < NEDGES) {
        atomicAdd(&d_cnt[NODES + src[e]], 1);   // out-degree
        atomicAdd(&d_cnt[dst[e]], 1);           // in-degree
    }
}

// exclusive scan of icnt -> rowptr, fused with per-node init (cursor/din/dout/g0)
__global__ void k_scan_init(const float* __restrict__ feat) {
    __shared__ int part[1024];
    const int CH = (NODES + 1023) / 1024;  // 98
    int tid = threadIdx.x;
    int s0 = tid * CH;
    int s1 = s0 + CH; if (s1 > NODES) s1 = NODES; if (s0 > NODES) s0 = NODES;
    int sum = 0;
    for (int i = s0; i < s1; i++) sum += d_cnt[i];
    part[tid] = sum;
    __syncthreads();
    for (int off = 1; off < 1024; off <<= 1) {
        int v = (tid >= off) ? part[tid - off] : 0;
        __syncthreads();
        part[tid] += v;
        __syncthreads();
    }
    int run = (tid > 0) ? part[tid - 1] : 0;
    for (int i = s0; i < s1; i++) {
        int ic = d_cnt[i];
        d_rowptr[i] = run;
        d_cursor[i] = run;
        float di = rsqrtf((float)(ic + 1));                 // +1 self-loop
        float dq = rsqrtf((float)(d_cnt[NODES + i] + 1));
        d_din[i]  = di;
        d_dout[i] = dq;
        d_g0[i]   = feat[i] * dq;                           // layer-0 source values
        run += ic;
    }
    if (tid == 1023) d_rowptr[NODES] = part[1023];
}

__global__ void k_scatter(const int* __restrict__ src, const int* __restrict__ dst) {
    int e = blockIdx.x * blockDim.x + threadIdx.x;
    if (e < NEDGES) {
        int p = atomicAdd(&d_cursor[dst[e]], 1);
        d_col[p] = src[e];
    }
}

// ---------------- layer 0 : scalar aggregation, D_in = 1 ----------------
__global__ void __launch_bounds__(256)
k_layer0(const float* __restrict__ W, const float* __restrict__ b) {
    const unsigned FULL = 0xffffffffu;
    int lane = threadIdx.x & 31;
    int w    = (blockIdx.x * blockDim.x + threadIdx.x) >> 5;
    int nw   = (gridDim.x * blockDim.x) >> 5;
    int tt   = lane < DD ? lane : 0;
    float wt = W[tt];
    float bt = b[tt];
    for (int n = w; n < NODES; n += nw) {
        int beg = d_rowptr[n], end = d_rowptr[n + 1];
        float acc = (lane == 0) ? d_g0[n] : 0.f;     // self-loop
        for (int j = beg + lane; j < end; j += 32)
            acc += __ldg(&d_g0[__ldg(&d_col[j])]);
        #pragma unroll
        for (int off = 16; off; off >>= 1)
            acc += __shfl_xor_sync(FULL, acc, off);
        if (lane < DD) {
            float r = fmaf(d_din[n] * acc, wt, bt);
            r = fmaxf(r, 0.f);
            d_gA[n * GSTR + lane] = r * d_dout[n];   // store g = h*dout (padded row)
        }
    }
}

// ---------------- fused layer: aggregate(g) -> @W -> *din +b -> (relu) -> (*dout) ----
// Padded input rows (1 L1 line per gather). W column in registers (spill-free at
// lb(256,4)=64 regs). s-vector broadcast via per-warp smem (1 STS + 5 LDS.128).
template <int RELU, int SCALE, int OSTR>
__device__ __forceinline__ void layer_body(const float* __restrict__ gin,
                                           float* __restrict__ gout,
                                           const float* __restrict__ W,
                                           const float* __restrict__ b) {
    const unsigned FULL = 0xffffffffu;
    __shared__ __align__(16) float ssm[8][DD];      // per-warp staging (8 warps/block)

    int lane = threadIdx.x & 31;
    int wid  = threadIdx.x >> 5;
    int w    = (blockIdx.x * blockDim.x + threadIdx.x) >> 5;
    int nw   = (gridDim.x * blockDim.x) >> 5;
    // lane layout for aggregation: 6 edges x 5 float4 chunks (lanes 30,31 idle)
    int c    = lane % 5;
    int esub = lane / 5;
    bool lok = lane < 30;
    int tt = lane < DD ? lane : 0;
    float wcol[DD];
    #pragma unroll
    for (int k = 0; k < DD; k++) wcol[k] = W[k * DD + tt];
    float bt = b[tt];
    const float4* gin4 = (const float4*)gin;        // 8 float4 per padded row
    float4* swarp = (float4*)ssm[wid];

    for (int n = w; n < NODES; n += nw) {
        int beg = d_rowptr[n], end = d_rowptr[n + 1];
        float4 acc = make_float4(0.f, 0.f, 0.f, 0.f);
        if (lok && esub == 0) acc = __ldg(&gin4[(n << 3) + c]);   // self-loop

        // ---- main loop: 18 edges / body, 3 rows in flight per lane ----
        int j0 = beg;
        if (lok) {
            for (; j0 + 18 <= end; j0 += 18) {
                int jj = j0 + esub;
                int s0 = __ldg(&d_col[jj]);
                int s1 = __ldg(&d_col[jj + 6]);
                int s2 = __ldg(&d_col[jj + 12]);
                float4 x0 = __ldg(&gin4[(s0 << 3) + c]);
                float4 x1 = __ldg(&gin4[(s1 << 3) + c]);
                float4 x2 = __ldg(&gin4[(s2 << 3) + c]);
                acc.x += x0.x; acc.y += x0.y; acc.z += x0.z; acc.w += x0.w;
                acc.x += x1.x; acc.y += x1.y; acc.z += x1.z; acc.w += x1.w;
                acc.x += x2.x; acc.y += x2.y; acc.z += x2.z; acc.w += x2.w;
            }
        } else {
            j0 = end - ((end - beg) % 18);           // loop-exit-consistent for lanes 30,31
            if (j0 < beg) j0 = beg;
        }

        // ---- remainder: up to 17 edges, predicated ----
        #pragma unroll 3
        for (; j0 < end; j0 += 6) {
            int j = j0 + esub;
            if (lok && j < end) {
                int s = __ldg(&d_col[j]);
                float4 x = __ldg(&gin4[(s << 3) + c]);
                acc.x += x.x; acc.y += x.y; acc.z += x.z; acc.w += x.w;
            }
        }

        // Reduce the 6 edge groups (stride 5), predicated folds (no double count):
        float4 t;
        t.x = __shfl_down_sync(FULL, acc.x, 15);
        t.y = __shfl_down_sync(FULL, acc.y, 15);
        t.z = __shfl_down_sync(FULL, acc.z, 15);
        t.w = __shfl_down_sync(FULL, acc.w, 15);
        if (lane < 15) { acc.x += t.x; acc.y += t.y; acc.z += t.z; acc.w += t.w; }
        t.x = __shfl_down_sync(FULL, acc.x, 10);
        t.y = __shfl_down_sync(FULL, acc.y, 10);
        t.z = __shfl_down_sync(FULL, acc.z, 10);
        t.w = __shfl_down_sync(FULL, acc.w, 10);
        if (lane < 5) { acc.x += t.x; acc.y += t.y; acc.z += t.z; acc.w += t.w; }
        t.x = __shfl_down_sync(FULL, acc.x, 5);
        t.y = __shfl_down_sync(FULL, acc.y, 5);
        t.z = __shfl_down_sync(FULL, acc.z, 5);
        t.w = __shfl_down_sync(FULL, acc.w, 5);
        if (lane < 5) { acc.x += t.x; acc.y += t.y; acc.z += t.z; acc.w += t.w; }

        // Broadcast s via per-warp smem: lanes 0-4 STS.128, then LDS.128 broadcasts.
        if (lane < 5) swarp[lane] = acc;
        __syncwarp(FULL);
        float m = 0.f;
        #pragma unroll
        for (int c2 = 0; c2 < 5; c2++) {
            float4 sv = swarp[c2];                   // same address all lanes: broadcast
            m = fmaf(sv.x, wcol[4 * c2 + 0], m);
            m = fmaf(sv.y, wcol[4 * c2 + 1], m);
            m = fmaf(sv.z, wcol[4 * c2 + 2], m);
            m = fmaf(sv.w, wcol[4 * c2 + 3], m);
        }
        __syncwarp(FULL);                            // protect staging from next node's STS
        if (lane < DD) {
            float r = fmaf(d_din[n], m, bt);
            if (RELU)  r = fmaxf(r, 0.f);
            if (SCALE) r *= d_dout[n];
            gout[n * OSTR + lane] = r;
        }
    }
}

__global__ void __launch_bounds__(256, 4)
k_layer_mid(const float* __restrict__ W, const float* __restrict__ b, int cur) {
    const float* gin = cur ? d_gB : d_gA;
    float* gout      = cur ? d_gA : d_gB;
    layer_body<1, 1, GSTR>(gin, gout, W, b);
}

__global__ void __launch_bounds__(256, 4)
k_layer_final(const float* __restrict__ W, const float* __restrict__ b,
              int cur, float* __restrict__ out) {
    const float* gin = cur ? d_gB : d_gA;
    layer_body<0, 0, DD>(gin, out, W, b);
}

// ---------------- launch ----------------
#define LGRID 1184

extern "C" void kernel_launch(void* const* d_in, const int* in_sizes, int n_in,
                              void* d_out, int out_size) {
    const float* feat = (const float*)d_in[0];
    const float* Ws   = (const float*)d_in[1];
    const float* bs   = (const float*)d_in[2];
    const float* Wm   = (const float*)d_in[3];
    const float* bm   = (const float*)d_in[4];
    const float* Wf   = (const float*)d_in[5];
    const float* bf   = (const float*)d_in[6];
    const int*   src  = (const int*)d_in[7];
    const int*   dst  = (const int*)d_in[8];
    float* out = (float*)d_out;

    // zero both degree counters with one async memset (graph-capturable)
    void* p_cnt = nullptr;
    cudaGetSymbolAddress(&p_cnt, d_cnt);
    cudaMemsetAsync(p_cnt, 0, 2 * NODES * sizeof(int));

    // graph build (CSR grouped by dst, self-loops implicit)
    k_hist     <<<(NEDGES + 255) / 256, 256>>>(src, dst);
    k_scan_init<<<1, 1024>>>(feat);
    k_scatter  <<<(NEDGES + 255) / 256, 256>>>(src, dst);

    // 20 conv layers, one fused kernel each
    k_layer0<<<LGRID, 256>>>(Ws, bs);                // writes d_gA (padded)
    int cur = 0;                                      // 0: current in gA
    for (int k = 0; k < 18; k++) {
        k_layer_mid<<<LGRID, 256>>>(Wm + k * DD * DD, bm + k * DD, cur);
        cur ^= 1;
    }
    k_layer_final<<<LGRID, 256>>>(Wf, bf, cur, out);
}

// round 8
// speedup vs baseline: 1.1924x; 1.0670x over previous
#include <cuda_runtime.h>

#define NODES 100000
#define NEDGES 3200000
#define DD 20

// ---------------- static device scratch (no allocations allowed) ----------------
__device__ int   d_cnt[2 * NODES];        // [0:N) icnt, [N:2N) ocnt  (one memset)
__device__ int   d_rowptr[NODES + 1];
__device__ int   d_cursor[NODES];
__device__ int   d_col[NEDGES];
__device__ float d_din[NODES];
__device__ float d_dout[NODES];
__device__ float d_g0[NODES];
__device__ float d_gA[NODES * DD];        // packed 20-float rows (R3-proven layout)
__device__ float d_gB[NODES * DD];
__device__ float d_s[NODES * DD];         // aggregated s-vectors (between agg/xform)

// ---------------- graph build ----------------
__global__ void k_hist(const int* __restrict__ src, const int* __restrict__ dst) {
    int e = blockIdx.x * blockDim.x + threadIdx.x;
    if (e < NEDGES) {
        atomicAdd(&d_cnt[NODES + src[e]], 1);   // out-degree
        atomicAdd(&d_cnt[dst[e]], 1);           // in-degree
    }
}

// exclusive scan of icnt -> rowptr, fused with per-node init (cursor/din/dout/g0)
__global__ void k_scan_init(const float* __restrict__ feat) {
    __shared__ int part[1024];
    const int CH = (NODES + 1023) / 1024;  // 98
    int tid = threadIdx.x;
    int s0 = tid * CH;
    int s1 = s0 + CH; if (s1 > NODES) s1 = NODES; if (s0 > NODES) s0 = NODES;
    int sum = 0;
    for (int i = s0; i < s1; i++) sum += d_cnt[i];
    part[tid] = sum;
    __syncthreads();
    for (int off = 1; off < 1024; off <<= 1) {
        int v = (tid >= off) ? part[tid - off] : 0;
        __syncthreads();
        part[tid] += v;
        __syncthreads();
    }
    int run = (tid > 0) ? part[tid - 1] : 0;
    for (int i = s0; i < s1; i++) {
        int ic = d_cnt[i];
        d_rowptr[i] = run;
        d_cursor[i] = run;
        float di = rsqrtf((float)(ic + 1));                 // +1 self-loop
        float dq = rsqrtf((float)(d_cnt[NODES + i] + 1));
        d_din[i]  = di;
        d_dout[i] = dq;
        d_g0[i]   = feat[i] * dq;                           // layer-0 source values
        run += ic;
    }
    if (tid == 1023) d_rowptr[NODES] = part[1023];
}

__global__ void k_scatter(const int* __restrict__ src, const int* __restrict__ dst) {
    int e = blockIdx.x * blockDim.x + threadIdx.x;
    if (e < NEDGES) {
        int p = atomicAdd(&d_cursor[dst[e]], 1);
        d_col[p] = src[e];
    }
}

// ---------------- layer 0 : scalar aggregation, D_in = 1 (fused, 26 regs) -----
__global__ void __launch_bounds__(256)
k_layer0(const float* __restrict__ W, const float* __restrict__ b) {
    const unsigned FULL = 0xffffffffu;
    int lane = threadIdx.x & 31;
    int w    = (blockIdx.x * blockDim.x + threadIdx.x) >> 5;
    int nw   = (gridDim.x * blockDim.x) >> 5;
    int tt   = lane < DD ? lane : 0;
    float wt = W[tt];
    float bt = b[tt];
    for (int n = w; n < NODES; n += nw) {
        int beg = d_rowptr[n], end = d_rowptr[n + 1];
        float acc = (lane == 0) ? d_g0[n] : 0.f;     // self-loop
        for (int j = beg + lane; j < end; j += 32)
            acc += __ldg(&d_g0[__ldg(&d_col[j])]);
        #pragma unroll
        for (int off = 16; off; off >>= 1)
            acc += __shfl_xor_sync(FULL, acc, off);
        if (lane < DD) {
            float r = fmaf(d_din[n] * acc, wt, bt);
            r = fmaxf(r, 0.f);
            d_gA[n * DD + lane] = r * d_dout[n];     // store g = h * dout
        }
    }
}

// ---------------- aggregation only: s[n] = g[n] + sum_{src in N(n)} g[src] ----
// No W, no matvec -> low regs -> __launch_bounds__(256,8) = 64 warps/SM.
__global__ void __launch_bounds__(256, 8)
k_agg(const float* __restrict__ gin, float* __restrict__ sout) {
    const unsigned FULL = 0xffffffffu;
    int lane = threadIdx.x & 31;
    int w    = (blockIdx.x * blockDim.x + threadIdx.x) >> 5;
    int nw   = (gridDim.x * blockDim.x) >> 5;
    // lane layout: 6 edges x 5 float4 chunks (lanes 30,31 idle)
    int c    = lane % 5;
    int esub = lane / 5;
    bool lok = lane < 30;
    const float4* gin4 = (const float4*)gin;    // packed rows: 5 float4 / node

    for (int n = w; n < NODES; n += nw) {
        int beg = d_rowptr[n], end = d_rowptr[n + 1];
        float4 acc = make_float4(0.f, 0.f, 0.f, 0.f);
        if (lok && esub == 0) acc = __ldg(&gin4[n * 5 + c]);   // self-loop

        // ---- main loop: 12 edges / body, 2 rows in flight per lane ----
        int j0 = beg;
        if (lok) {
            for (; j0 + 12 <= end; j0 += 12) {
                int jj = j0 + esub;
                int s0 = __ldg(&d_col[jj]);
                int s1 = __ldg(&d_col[jj + 6]);
                float4 x0 = __ldg(&gin4[s0 * 5 + c]);
                float4 x1 = __ldg(&gin4[s1 * 5 + c]);
                acc.x += x0.x; acc.y += x0.y; acc.z += x0.z; acc.w += x0.w;
                acc.x += x1.x; acc.y += x1.y; acc.z += x1.z; acc.w += x1.w;
            }
        } else {
            j0 = end - ((end - beg) % 12);           // loop-exit-consistent for lanes 30,31
            if (j0 < beg) j0 = beg;
        }

        // ---- remainder: up to 11 edges, predicated ----
        #pragma unroll 2
        for (; j0 < end; j0 += 6) {
            int j = j0 + esub;
            if (lok && j < end) {
                int s = __ldg(&d_col[j]);
                float4 x = __ldg(&gin4[s * 5 + c]);
                acc.x += x.x; acc.y += x.y; acc.z += x.z; acc.w += x.w;
            }
        }

        // Reduce 6 edge groups (stride 5), predicated folds (no double count):
        float4 t;
        t.x = __shfl_down_sync(FULL, acc.x, 15);
        t.y = __shfl_down_sync(FULL, acc.y, 15);
        t.z = __shfl_down_sync(FULL, acc.z, 15);
        t.w = __shfl_down_sync(FULL, acc.w, 15);
        if (lane < 15) { acc.x += t.x; acc.y += t.y; acc.z += t.z; acc.w += t.w; }
        t.x = __shfl_down_sync(FULL, acc.x, 10);
        t.y = __shfl_down_sync(FULL, acc.y, 10);
        t.z = __shfl_down_sync(FULL, acc.z, 10);
        t.w = __shfl_down_sync(FULL, acc.w, 10);
        if (lane < 5) { acc.x += t.x; acc.y += t.y; acc.z += t.z; acc.w += t.w; }
        t.x = __shfl_down_sync(FULL, acc.x, 5);
        t.y = __shfl_down_sync(FULL, acc.y, 5);
        t.z = __shfl_down_sync(FULL, acc.z, 5);
        t.w = __shfl_down_sync(FULL, acc.w, 5);
        if (lane < 5) { acc.x += t.x; acc.y += t.y; acc.z += t.z; acc.w += t.w; }

        // lanes 0-4 write the 80B s row (contiguous float4 stores)
        if (lane < 5)
            ((float4*)(sout + n * DD))[lane] = acc;
    }
}

// ---------------- dense transform: g = (relu(din*s@W + b)) * dout -------------
// Thread-per-node; W/b broadcast from smem (no gather pressure here).
template <int RELU, int SCALE>
__global__ void __launch_bounds__(256, 4)
k_xform(const float* __restrict__ sin, float* __restrict__ gout,
        const float* __restrict__ W, const float* __restrict__ b) {
    __shared__ float Wsm[DD * DD];
    __shared__ float bsm[DD];
    for (int i = threadIdx.x; i < DD * DD; i += blockDim.x) Wsm[i] = W[i];
    if (threadIdx.x < DD) bsm[threadIdx.x] = b[threadIdx.x];
    __syncthreads();

    int n = blockIdx.x * blockDim.x + threadIdx.x;
    if (n >= NODES) return;

    const float4* srow = (const float4*)(sin + n * DD);
    float s[DD];
    #pragma unroll
    for (int q = 0; q < 5; q++) {
        float4 v = __ldg(&srow[q]);
        s[4 * q + 0] = v.x; s[4 * q + 1] = v.y; s[4 * q + 2] = v.z; s[4 * q + 3] = v.w;
    }
    float din = d_din[n];
    float dq  = d_dout[n];

    float o[DD];
    #pragma unroll
    for (int k = 0; k < DD; k++) o[k] = 0.f;
    #pragma unroll
    for (int j = 0; j < DD; j++) {
        float sj = s[j];
        #pragma unroll
        for (int k = 0; k < DD; k++)
            o[k] = fmaf(sj, Wsm[j * DD + k], o[k]);   // Wsm broadcast across lanes
    }

    float4* orow = (float4*)(gout + n * DD);
    #pragma unroll
    for (int q = 0; q < 5; q++) {
        float r0 = fmaf(din, o[4 * q + 0], bsm[4 * q + 0]);
        float r1 = fmaf(din, o[4 * q + 1], bsm[4 * q + 1]);
        float r2 = fmaf(din, o[4 * q + 2], bsm[4 * q + 2]);
        float r3 = fmaf(din, o[4 * q + 3], bsm[4 * q + 3]);
        if (RELU) { r0 = fmaxf(r0, 0.f); r1 = fmaxf(r1, 0.f); r2 = fmaxf(r2, 0.f); r3 = fmaxf(r3, 0.f); }
        if (SCALE) { r0 *= dq; r1 *= dq; r2 *= dq; r3 *= dq; }
        float4 v; v.x = r0; v.y = r1; v.z = r2; v.w = r3;
        orow[q] = v;
    }
}

// ---------------- launch ----------------
#define LGRID 1184
#define XGRID ((NODES + 255) / 256)

extern "C" void kernel_launch(void* const* d_in, const int* in_sizes, int n_in,
                              void* d_out, int out_size) {
    const float* feat = (const float*)d_in[0];
    const float* Ws   = (const float*)d_in[1];
    const float* bs   = (const float*)d_in[2];
    const float* Wm   = (const float*)d_in[3];
    const float* bm   = (const float*)d_in[4];
    const float* Wf   = (const float*)d_in[5];
    const float* bf   = (const float*)d_in[6];
    const int*   src  = (const int*)d_in[7];
    const int*   dst  = (const int*)d_in[8];
    float* out = (float*)d_out;

    // resolve device-symbol addresses (host API, capture-safe)
    void *pA, *pB, *pS, *pCnt;
    cudaGetSymbolAddress(&pA, d_gA);
    cudaGetSymbolAddress(&pB, d_gB);
    cudaGetSymbolAddress(&pS, d_s);
    cudaGetSymbolAddress(&pCnt, d_cnt);
    float* gA = (float*)pA;
    float* gB = (float*)pB;
    float* sv = (float*)pS;

    // zero both degree counters with one async memset (graph-capturable)
    cudaMemsetAsync(pCnt, 0, 2 * NODES * sizeof(int));

    // graph build (CSR grouped by dst, self-loops implicit)
    k_hist     <<<(NEDGES + 255) / 256, 256>>>(src, dst);
    k_scan_init<<<1, 1024>>>(feat);
    k_scatter  <<<(NEDGES + 255) / 256, 256>>>(src, dst);

    // layer 0 fused (scalar gather), then 19 x (agg -> xform)
    k_layer0<<<LGRID, 256>>>(Ws, bs);                // writes d_gA
    int cur = 0;                                      // current activations in gA
    for (int k = 0; k < 18; k++) {
        const float* gin = cur ? gB : gA;
        float* gout      = cur ? gA : gB;
        k_agg<<<LGRID, 256>>>(gin, sv);
        k_xform<1, 1><<<XGRID, 256>>>(sv, gout, Wm + k * DD * DD, bm + k * DD);
        cur ^= 1;
    }
    const float* gin = cur ? gB : gA;
    k_agg<<<LGRID, 256>>>(gin, sv);
    k_xform<0, 0><<<XGRID, 256>>>(sv, out, Wf, bf);
}